// round 7
// baseline (speedup 1.0000x reference)
#include <cuda_runtime.h>
#include <stdint.h>

#define V_N    1024
#define EDGE_N 6144
#define MAXD   64

// ---- static device scratch (no allocation allowed) ----
__device__ uint16_t g_e2v[EDGE_N];
__device__ __align__(16) int g_deg[V_N];
__device__ __align__(16) uint16_t g_ell[MAXD * V_N];   // column-major ELL: ell[j*V_N + v]

// K1: sentinel-fill ELL, zero degrees, recover edge->vnode from one-hot mask.
__global__ void k_prep(const float4* __restrict__ mask4) {
    int stride = gridDim.x * blockDim.x;
    int tid0 = blockIdx.x * blockDim.x + threadIdx.x;
    for (int i = tid0; i < MAXD * V_N; i += stride) g_ell[i] = (uint16_t)EDGE_N;
    for (int i = tid0; i < V_N; i += stride) g_deg[i] = 0;
    for (int i = tid0; i < (EDGE_N * V_N) / 4; i += stride) {
        float4 m = mask4[i];
        int base = i * 4;
        if (m.x != 0.0f) g_e2v[base >> 10]       = (uint16_t)( base      & (V_N - 1));
        if (m.y != 0.0f) g_e2v[(base + 1) >> 10] = (uint16_t)((base + 1) & (V_N - 1));
        if (m.z != 0.0f) g_e2v[(base + 2) >> 10] = (uint16_t)((base + 2) & (V_N - 1));
        if (m.w != 0.0f) g_e2v[(base + 3) >> 10] = (uint16_t)((base + 3) & (V_N - 1));
    }
}

// K2: one WARP per edge. rank(e) = |{e' < e : e2v[e']==e2v[e]}| via lane-strided
// smem scan + warp reduce. Deterministic stable placement in ascending edge order.
__global__ __launch_bounds__(256) void k_build() {
    __shared__ uint16_t se[EDGE_N];
    int t = threadIdx.x;
    const uint32_t* src = (const uint32_t*)g_e2v;
    uint32_t* dst = (uint32_t*)se;
    #pragma unroll
    for (int i = 0; i < EDGE_N / 2 / 256; ++i)
        dst[i * 256 + t] = src[i * 256 + t];
    __syncthreads();

    int e = (blockIdx.x * blockDim.x + t) >> 5;
    int lane = t & 31;
    if (e < EDGE_N) {
        int v = se[e];
        int cnt = 0;
        for (int i = lane; i < e; i += 32) cnt += (se[i] == v);
        cnt = __reduce_add_sync(0xffffffff, cnt);
        if (lane == 0) {
            g_ell[cnt * V_N + v] = (uint16_t)e;
            atomicAdd(&g_deg[v], 1);
        }
    }
}

// swizzle: bijective, touches bits 0-2 only (6144 = 0x1800 unaffected),
// makes the staging STS.128 pattern conflict-free across 8-lane phases.
__device__ __forceinline__ int swz(int e) { return e ^ ((e >> 2) & 7); }

// Main: one block per FOUR batch rows. stage[m(e)] = float4{r0[e],r1[e],r2[e],r3[e]}.
// One random LDS.128 serves 4 rows. Thread t owns vnodes 4t..4t+3; ushort4 index
// loads coalesced & L1-resident; sentinel stage[6144]=0 makes padding branch-free.
__global__ __launch_bounds__(256) void k_main(
    const float* __restrict__ fin, const float* __restrict__ fprev,
    float* __restrict__ out, int B)
{
    extern __shared__ __align__(16) float4 stage[];   // (EDGE_N+1) float4 = 98320 B
    int t = threadIdx.x;
    long long b0 = (long long)blockIdx.x * 4;
    long long i1 = (b0 + 1 < B) ? b0 + 1 : b0;
    long long i2 = (b0 + 2 < B) ? b0 + 2 : b0;
    long long i3 = (b0 + 3 < B) ? b0 + 3 : b0;

    const float4* r0 = (const float4*)(fprev + b0 * EDGE_N);
    const float4* r1 = (const float4*)(fprev + i1 * EDGE_N);
    const float4* r2 = (const float4*)(fprev + i2 * EDGE_N);
    const float4* r3 = (const float4*)(fprev + i3 * EDGE_N);
    #pragma unroll
    for (int i = 0; i < EDGE_N / 1024; ++i) {         // 6 chunks
        int u = i * 256 + t;
        float4 a = r0[u], b = r1[u], c = r2[u], d = r3[u];
        int base = u * 4;
        stage[swz(base + 0)] = make_float4(a.x, b.x, c.x, d.x);
        stage[swz(base + 1)] = make_float4(a.y, b.y, c.y, d.y);
        stage[swz(base + 2)] = make_float4(a.z, b.z, c.z, d.z);
        stage[swz(base + 3)] = make_float4(a.w, b.w, c.w, d.w);
    }
    if (t == 0) stage[EDGE_N] = make_float4(0.f, 0.f, 0.f, 0.f);

    float4 s0 = ((const float4*)(fin + b0 * V_N))[t];
    float4 s1 = ((const float4*)(fin + i1 * V_N))[t];
    float4 s2 = ((const float4*)(fin + i2 * V_N))[t];
    float4 s3 = ((const float4*)(fin + i3 * V_N))[t];
    int4 dg = ((const int4*)g_deg)[t];
    int md = max(max(dg.x, dg.y), max(dg.z, dg.w));

    __syncthreads();

    const ushort4* ellp = (const ushort4*)g_ell;
    #pragma unroll 2
    for (int j = 0; j < md; ++j) {
        ushort4 e = ellp[j * (V_N / 4) + t];
        float4 vx = stage[swz(e.x)];
        float4 vy = stage[swz(e.y)];
        float4 vz = stage[swz(e.z)];
        float4 vw = stage[swz(e.w)];
        s0.x += vx.x; s1.x += vx.y; s2.x += vx.z; s3.x += vx.w;
        s0.y += vy.x; s1.y += vy.y; s2.y += vy.z; s3.y += vy.w;
        s0.z += vz.x; s1.z += vz.y; s2.z += vz.z; s3.z += vz.w;
        s0.w += vw.x; s1.w += vw.y; s2.w += vw.z; s3.w += vw.w;
    }

    ((float4*)(out + b0 * V_N))[t] = s0;
    ((float4*)(out + i1 * V_N))[t] = s1;
    ((float4*)(out + i2 * V_N))[t] = s2;
    ((float4*)(out + i3 * V_N))[t] = s3;
}

extern "C" void kernel_launch(void* const* d_in, const int* in_sizes, int n_in,
                              void* d_out, int out_size) {
    const float* fin   = (const float*)d_in[0];   // [B, V_N]
    const float* fprev = (const float*)d_in[1];   // [B, EDGE_N]
    const float* mask  = (const float*)d_in[2];   // [EDGE_N, V_N]
    int B = in_sizes[0] / V_N;

    static const int kSmem = (EDGE_N + 1) * sizeof(float4);   // 98320 B
    cudaFuncSetAttribute(k_main, cudaFuncAttributeMaxDynamicSharedMemorySize, kSmem);

    k_prep <<<2048, 256>>>((const float4*)mask);
    k_build<<<(EDGE_N * 32) / 256, 256>>>();
    k_main <<<(B + 3) / 4, 256, kSmem>>>(fin, fprev, (float*)d_out, B);
}